// round 1
// baseline (speedup 1.0000x reference)
#include <cuda_runtime.h>
#include <cstdint>

#define NN   500000
#define EE   4000000
#define FIN  24
#define HH   64
#define KC   6
#define OD   6
#define EPSBN 1e-5f

// ---------------- static scratch (no runtime allocation allowed) ----------------
__device__ int   g_deg[NN];
__device__ float g_dis[NN];
__device__ float g_norm[EE];
__device__ float g_T[5][NN * FIN];          // T1..T5 (T0 == x input)
__device__ float g_h[(size_t)NN * HH];      // conv output before BN
__device__ float g_sum[HH];
__device__ float g_sumsq[HH];
__device__ float g_scale[HH];
__device__ float g_shift[HH];

// ---------------- helpers ----------------
__device__ __forceinline__ void red4(float4* p, float a, float b, float c, float d) {
    asm volatile("red.global.add.v4.f32 [%0], {%1, %2, %3, %4};"
                 :: "l"(p), "f"(a), "f"(b), "f"(c), "f"(d) : "memory");
}

// ---------------- kernels ----------------
__global__ void k_zero() {
    int i = blockIdx.x * blockDim.x + threadIdx.x;
    if (i < NN) g_deg[i] = 0;
    if (i < HH) { g_sum[i] = 0.f; g_sumsq[i] = 0.f; }
}

__global__ void k_deg(const int* __restrict__ col) {
    int e = blockIdx.x * blockDim.x + threadIdx.x;
    if (e < EE) atomicAdd(&g_deg[col[e]], 1);
}

__global__ void k_dis() {
    int i = blockIdx.x * blockDim.x + threadIdx.x;
    if (i < NN) {
        int d = g_deg[i];
        g_dis[i] = (d > 0) ? rsqrtf((float)d) : 0.f;
    }
}

__global__ void k_norm(const int* __restrict__ row, const int* __restrict__ col) {
    int e = blockIdx.x * blockDim.x + threadIdx.x;
    if (e < EE) g_norm[e] = -g_dis[row[e]] * g_dis[col[e]];
}

// dst = m * src  (m==0 -> zero fill; m==-1 -> negate for the Chebyshev combine fold)
__global__ void k_init(int dsti, int srci, const float* __restrict__ x, float m) {
    int i = blockIdx.x * blockDim.x + threadIdx.x;
    if (i >= NN * FIN / 4) return;
    float4 o;
    if (m == 0.f) {
        o = make_float4(0.f, 0.f, 0.f, 0.f);
    } else {
        const float4* s = (const float4*)(srci < 0 ? x : g_T[srci]);
        float4 v = __ldg(s + i);
        o = make_float4(m * v.x, m * v.y, m * v.z, m * v.w);
    }
    ((float4*)g_T[dsti])[i] = o;
}

// dst[col] += scl * norm[e] * src[row]   (gather-scale-scatter, vector reductions)
__global__ void k_prop(int dsti, int srci, const float* __restrict__ x,
                       const int* __restrict__ row, const int* __restrict__ col,
                       float scl) {
    int e = blockIdx.x * blockDim.x + threadIdx.x;
    if (e >= EE) return;
    int r = row[e];
    int c = col[e];
    float w = scl * g_norm[e];
    const float* sp = (srci < 0 ? x : g_T[srci]) + (size_t)r * FIN;
    float*       dp = g_T[dsti] + (size_t)c * FIN;
    const float4* s4 = (const float4*)sp;
    float4*       d4 = (float4*)dp;
#pragma unroll
    for (int i = 0; i < 6; i++) {
        float4 v = __ldg(s4 + i);
        red4(d4 + i, w * v.x, w * v.y, w * v.z, w * v.w);
    }
}

// h = [x|T1..T5] @ W[144,64] + b1 ; also accumulate BN batch stats
__global__ __launch_bounds__(128) void k_gemm(const float* __restrict__ x,
                                              const float* __restrict__ W1,
                                              const float* __restrict__ b1) {
    __shared__ float sW[KC * FIN * HH];   // 9216 floats = 36 KB
    __shared__ float sRs[4][HH];
    __shared__ float sRq[4][HH];

    int tid = threadIdx.x;
    for (int i = tid; i < KC * FIN * HH; i += 128) sW[i] = W1[i];
    __syncthreads();

    int n = blockIdx.x * 128 + tid;
    bool valid = (n < NN);

    float acc[HH];
#pragma unroll
    for (int j = 0; j < HH; j++) acc[j] = 0.f;

    if (valid) {
#pragma unroll
        for (int k = 0; k < KC; k++) {
            const float* sp = (k == 0 ? x : g_T[k - 1]) + (size_t)n * FIN;
            const float4* s4 = (const float4*)sp;
#pragma unroll
            for (int i4 = 0; i4 < 6; i4++) {
                float4 v = __ldg(s4 + i4);
                const float* wr = &sW[(k * FIN + i4 * 4) * HH];
                const float4* w0 = (const float4*)(wr);
                const float4* w1 = (const float4*)(wr + HH);
                const float4* w2 = (const float4*)(wr + 2 * HH);
                const float4* w3 = (const float4*)(wr + 3 * HH);
#pragma unroll
                for (int j4 = 0; j4 < 16; j4++) {
                    float4 a0 = w0[j4], a1 = w1[j4], a2 = w2[j4], a3 = w3[j4];
                    acc[4 * j4 + 0] += v.x * a0.x + v.y * a1.x + v.z * a2.x + v.w * a3.x;
                    acc[4 * j4 + 1] += v.x * a0.y + v.y * a1.y + v.z * a2.y + v.w * a3.y;
                    acc[4 * j4 + 2] += v.x * a0.z + v.y * a1.z + v.z * a2.z + v.w * a3.z;
                    acc[4 * j4 + 3] += v.x * a0.w + v.y * a1.w + v.z * a2.w + v.w * a3.w;
                }
            }
        }
#pragma unroll
        for (int j = 0; j < HH; j++) acc[j] += __ldg(&b1[j]);

        float4* hp = (float4*)(g_h + (size_t)n * HH);
#pragma unroll
        for (int j4 = 0; j4 < 16; j4++)
            hp[j4] = make_float4(acc[4 * j4], acc[4 * j4 + 1], acc[4 * j4 + 2], acc[4 * j4 + 3]);
    }

    // BN batch statistics: warp shfl reduce, then block combine, then 128 atomics/block
    int lane = tid & 31, wid = tid >> 5;
#pragma unroll
    for (int j = 0; j < HH; j++) {
        float s = acc[j];
        float q = acc[j] * acc[j];
#pragma unroll
        for (int off = 16; off > 0; off >>= 1) {
            s += __shfl_xor_sync(0xffffffffu, s, off);
            q += __shfl_xor_sync(0xffffffffu, q, off);
        }
        if (lane == 0) { sRs[wid][j] = s; sRq[wid][j] = q; }
    }
    __syncthreads();
    if (tid < HH) {
        float a = sRs[0][tid] + sRs[1][tid] + sRs[2][tid] + sRs[3][tid];
        float b = sRq[0][tid] + sRq[1][tid] + sRq[2][tid] + sRq[3][tid];
        atomicAdd(&g_sum[tid], a);
        atomicAdd(&g_sumsq[tid], b);
    }
}

__global__ void k_bnparam(const float* __restrict__ gamma, const float* __restrict__ beta) {
    int j = threadIdx.x;
    if (j < HH) {
        float inv_n = 1.f / (float)NN;
        float mean = g_sum[j] * inv_n;
        float var  = g_sumsq[j] * inv_n - mean * mean;
        float rstd = rsqrtf(var + EPSBN);
        float sc = gamma[j] * rstd;
        g_scale[j] = sc;
        g_shift[j] = beta[j] - mean * sc;
    }
}

// y = relu(h*scale + shift) @ Wmix[64,6] + bmix
__global__ __launch_bounds__(256) void k_final(const float* __restrict__ Wmix,
                                               const float* __restrict__ bmix,
                                               float* __restrict__ out) {
    __shared__ float sWm[HH * OD];
    __shared__ float sSc[HH], sSh[HH], sB[OD];
    int tid = threadIdx.x;
    for (int i = tid; i < HH * OD; i += 256) sWm[i] = Wmix[i];
    if (tid < HH) { sSc[tid] = g_scale[tid]; sSh[tid] = g_shift[tid]; }
    if (tid < OD) sB[tid] = bmix[tid];
    __syncthreads();

    int n = blockIdx.x * 256 + tid;
    if (n >= NN) return;

    float o0 = sB[0], o1 = sB[1], o2 = sB[2], o3 = sB[3], o4 = sB[4], o5 = sB[5];
    const float4* hp = (const float4*)(g_h + (size_t)n * HH);
#pragma unroll
    for (int j4 = 0; j4 < 16; j4++) {
        float4 hv = hp[j4];
        float hv4[4] = {hv.x, hv.y, hv.z, hv.w};
#pragma unroll
        for (int t = 0; t < 4; t++) {
            int j = 4 * j4 + t;
            float val = fmaxf(hv4[t] * sSc[j] + sSh[j], 0.f);
            const float* wm = &sWm[j * OD];
            o0 += val * wm[0]; o1 += val * wm[1]; o2 += val * wm[2];
            o3 += val * wm[3]; o4 += val * wm[4]; o5 += val * wm[5];
        }
    }
    float* op = out + (size_t)n * OD;
    op[0] = o0; op[1] = o1; op[2] = o2; op[3] = o3; op[4] = o4; op[5] = o5;
}

// ---------------- launch ----------------
extern "C" void kernel_launch(void* const* d_in, const int* in_sizes, int n_in,
                              void* d_out, int out_size) {
    const float* x     = (const float*)d_in[0];
    const int*   ei    = (const int*)  d_in[1];
    const float* W1    = (const float*)d_in[2];
    const float* b1    = (const float*)d_in[3];
    const float* gamma = (const float*)d_in[4];
    const float* beta  = (const float*)d_in[5];
    const float* Wmix  = (const float*)d_in[6];
    const float* bmix  = (const float*)d_in[7];
    float* out = (float*)d_out;

    const int* row = ei;        // edge_index[0]
    const int* col = ei + EE;   // edge_index[1]

    const int TB = 256;
    int gN  = (NN + TB - 1) / TB;
    int gE  = (EE + TB - 1) / TB;
    int gI  = (NN * FIN / 4 + TB - 1) / TB;

    k_zero<<<gN, TB>>>();
    k_deg<<<gE, TB>>>(col);
    k_dis<<<gN, TB>>>();
    k_norm<<<gE, TB>>>(row, col);

    // T1 = prop(x)
    k_init<<<gI, TB>>>(0, -1, x, 0.f);
    k_prop<<<gE, TB>>>(0, -1, x, row, col, 1.f);
    // T2 = 2*prop(T1) - x
    k_init<<<gI, TB>>>(1, -1, x, -1.f);
    k_prop<<<gE, TB>>>(1, 0, x, row, col, 2.f);
    // T3 = 2*prop(T2) - T1
    k_init<<<gI, TB>>>(2, 0, x, -1.f);
    k_prop<<<gE, TB>>>(2, 1, x, row, col, 2.f);
    // T4 = 2*prop(T3) - T2
    k_init<<<gI, TB>>>(3, 1, x, -1.f);
    k_prop<<<gE, TB>>>(3, 2, x, row, col, 2.f);
    // T5 = 2*prop(T4) - T3
    k_init<<<gI, TB>>>(4, 2, x, -1.f);
    k_prop<<<gE, TB>>>(4, 3, x, row, col, 2.f);

    // stacked GEMM + BN stats
    k_gemm<<<(NN + 127) / 128, 128>>>(x, W1, b1);
    k_bnparam<<<1, HH>>>(gamma, beta);
    k_final<<<(NN + TB - 1) / TB, TB>>>(Wmix, bmix, out);
}

// round 2
// speedup vs baseline: 1.1740x; 1.1740x over previous
#include <cuda_runtime.h>
#include <cstdint>

#define NN   500000
#define EE   4000000
#define FIN  24
#define HH   64
#define KC   6
#define OD   6
#define EPSBN 1e-5f

// ---------------- static scratch ----------------
__device__ int   g_deg[NN];
__device__ float g_dis[NN];
__device__ float g_norm[EE];
__device__ float g_T[5][NN * FIN];          // T1..T5 (T0 == x input)
__device__ float g_h[(size_t)NN * HH];      // conv output before BN
__device__ float g_sum[HH];
__device__ float g_sumsq[HH];
__device__ float g_scale[HH];
__device__ float g_shift[HH];

// ---------------- helpers ----------------
__device__ __forceinline__ void red4(float4* p, float a, float b, float c, float d) {
    asm volatile("red.global.add.v4.f32 [%0], {%1, %2, %3, %4};"
                 :: "l"(p), "f"(a), "f"(b), "f"(c), "f"(d) : "memory");
}
__device__ __forceinline__ unsigned long long pack2(float lo, float hi) {
    unsigned long long r;
    asm("mov.b64 %0, {%1, %2};" : "=l"(r) : "f"(lo), "f"(hi));
    return r;
}
__device__ __forceinline__ void unpack2(unsigned long long v, float& lo, float& hi) {
    asm("mov.b64 {%0, %1}, %2;" : "=f"(lo), "=f"(hi) : "l"(v));
}
__device__ __forceinline__ void ffma2(unsigned long long& d, unsigned long long a,
                                      unsigned long long b) {
    asm("fma.rn.f32x2 %0, %1, %2, %0;" : "+l"(d) : "l"(a), "l"(b));
}

// ---------------- kernels ----------------
__global__ void k_zero() {
    int i = blockIdx.x * blockDim.x + threadIdx.x;
    if (i < NN) g_deg[i] = 0;
    if (i < HH) { g_sum[i] = 0.f; g_sumsq[i] = 0.f; }
}

__global__ void k_deg(const int4* __restrict__ col4) {
    int i = blockIdx.x * blockDim.x + threadIdx.x;
    if (i >= EE / 4) return;
    int4 c = __ldg(col4 + i);
    atomicAdd(&g_deg[c.x], 1);
    atomicAdd(&g_deg[c.y], 1);
    atomicAdd(&g_deg[c.z], 1);
    atomicAdd(&g_deg[c.w], 1);
}

__global__ void k_dis() {
    int i = blockIdx.x * blockDim.x + threadIdx.x;
    if (i < NN) {
        int d = g_deg[i];
        g_dis[i] = (d > 0) ? rsqrtf((float)d) : 0.f;
    }
}

__global__ void k_norm(const int4* __restrict__ row4, const int4* __restrict__ col4) {
    int i = blockIdx.x * blockDim.x + threadIdx.x;
    if (i >= EE / 4) return;
    int4 r = __ldg(row4 + i);
    int4 c = __ldg(col4 + i);
    float4 o;
    o.x = -g_dis[r.x] * g_dis[c.x];
    o.y = -g_dis[r.y] * g_dis[c.y];
    o.z = -g_dis[r.z] * g_dis[c.z];
    o.w = -g_dis[r.w] * g_dis[c.w];
    ((float4*)g_norm)[i] = o;
}

// dst = m * src  (m==0 -> zero fill; m==-1 -> negate for Chebyshev combine fold)
__global__ void k_init(int dsti, int srci, const float* __restrict__ x, float m) {
    int i = blockIdx.x * blockDim.x + threadIdx.x;
    if (i >= NN * FIN / 4) return;
    float4 o;
    if (m == 0.f) {
        o = make_float4(0.f, 0.f, 0.f, 0.f);
    } else {
        const float4* s = (const float4*)(srci < 0 ? x : g_T[srci]);
        float4 v = __ldg(s + i);
        o = make_float4(m * v.x, m * v.y, m * v.z, m * v.w);
    }
    ((float4*)g_T[dsti])[i] = o;
}

// dst[col] += scl * norm[e] * src[row] ; 2 lanes per edge, 3 float4 each
__global__ __launch_bounds__(256) void k_prop(int dsti, int srci,
                                              const float* __restrict__ x,
                                              const int* __restrict__ row,
                                              const int* __restrict__ col,
                                              float scl) {
    int t = blockIdx.x * blockDim.x + threadIdx.x;
    int e = t >> 1;
    if (e >= EE) return;
    int h = t & 1;
    int r = __ldg(row + e);
    int c = __ldg(col + e);
    float w = scl * __ldg(&g_norm[e]);
    const float4* s4 = (const float4*)((srci < 0 ? x : g_T[srci]) + (size_t)r * FIN) + h * 3;
    float4*       d4 = (float4*)(g_T[dsti] + (size_t)c * FIN) + h * 3;
    float4 v0 = __ldg(s4 + 0);
    float4 v1 = __ldg(s4 + 1);
    float4 v2 = __ldg(s4 + 2);
    red4(d4 + 0, w * v0.x, w * v0.y, w * v0.z, w * v0.w);
    red4(d4 + 1, w * v1.x, w * v1.y, w * v1.z, w * v1.w);
    red4(d4 + 2, w * v2.x, w * v2.y, w * v2.z, w * v2.w);
}

// h = [x|T1..T5] @ W[144,64] + b1 ; packed f32x2 math, 2 nodes/thread, H split in half
// thread t: nodes n0 = base + (t>>1)*2, n0+1 ; j-range = (t&1)*32 .. +32
__global__ __launch_bounds__(128) void k_gemm(const float* __restrict__ x,
                                              const float* __restrict__ W1,
                                              const float* __restrict__ b1) {
    __shared__ float sW[KC * FIN * HH];   // 36 KB
    __shared__ float sRs[4][HH];
    __shared__ float sRq[4][HH];

    int tid = threadIdx.x;
    for (int i = tid; i < KC * FIN * HH; i += 128) sW[i] = W1[i];
    __syncthreads();

    int half = tid & 1;                       // which 32-wide half of H
    int n0 = blockIdx.x * 128 + (tid >> 1) * 2;  // 64 nodes per block
    int n1 = n0 + 1;
    bool v0 = (n0 < NN), v1 = (n1 < NN);

    unsigned long long acc0[16], acc1[16];
#pragma unroll
    for (int j = 0; j < 16; j++) { acc0[j] = 0ull; acc1[j] = 0ull; }

#pragma unroll
    for (int k = 0; k < KC; k++) {
        const float* base = (k == 0 ? x : g_T[k - 1]);
        const float4* s40 = (const float4*)(base + (size_t)n0 * FIN);
        const float4* s41 = (const float4*)(base + (size_t)n1 * FIN);
#pragma unroll
        for (int i4 = 0; i4 < 6; i4++) {
            float4 a = v0 ? __ldg(s40 + i4) : make_float4(0.f, 0.f, 0.f, 0.f);
            float4 b = v1 ? __ldg(s41 + i4) : make_float4(0.f, 0.f, 0.f, 0.f);
            float av[4] = {a.x, a.y, a.z, a.w};
            float bv[4] = {b.x, b.y, b.z, b.w};
#pragma unroll
            for (int t = 0; t < 4; t++) {
                int i = i4 * 4 + t;
                unsigned long long pa = pack2(av[t], av[t]);
                unsigned long long pb = pack2(bv[t], bv[t]);
                const unsigned long long* wr =
                    (const unsigned long long*)&sW[(k * FIN + i) * HH + half * 32];
#pragma unroll
                for (int j = 0; j < 16; j++) {
                    unsigned long long wj = wr[j];
                    ffma2(acc0[j], pa, wj);
                    ffma2(acc1[j], pb, wj);
                }
            }
        }
    }

    // add bias, write h, accumulate local BN stats
    float s[32], q[32];
#pragma unroll
    for (int j = 0; j < 16; j++) {
        float b0 = __ldg(&b1[half * 32 + 2 * j]);
        float b1v = __ldg(&b1[half * 32 + 2 * j + 1]);
        float a0, a1c, c0, c1;
        unpack2(acc0[j], a0, a1c);
        unpack2(acc1[j], c0, c1);
        a0 += b0; a1c += b1v; c0 += b0; c1 += b1v;
        s[2 * j]     = (v0 ? a0 : 0.f) + (v1 ? c0 : 0.f);
        s[2 * j + 1] = (v0 ? a1c : 0.f) + (v1 ? c1 : 0.f);
        q[2 * j]     = (v0 ? a0 * a0 : 0.f) + (v1 ? c0 * c0 : 0.f);
        q[2 * j + 1] = (v0 ? a1c * a1c : 0.f) + (v1 ? c1 * c1 : 0.f);
        if (v0) ((float2*)(g_h + (size_t)n0 * HH + half * 32))[j] = make_float2(a0, a1c);
        if (v1) ((float2*)(g_h + (size_t)n1 * HH + half * 32))[j] = make_float2(c0, c1);
    }

    // reduce across the 16 lanes of this warp that share `half`
    int lane = tid & 31, wid = tid >> 5;
#pragma unroll
    for (int j = 0; j < 32; j++) {
        float sv = s[j], qv = q[j];
#pragma unroll
        for (int off = 2; off < 32; off <<= 1) {
            sv += __shfl_xor_sync(0xffffffffu, sv, off);
            qv += __shfl_xor_sync(0xffffffffu, qv, off);
        }
        if ((lane >> 1) == 0) {   // lane 0 (half 0) and lane 1 (half 1)
            sRs[wid][(lane & 1) * 32 + j] = sv;
            sRq[wid][(lane & 1) * 32 + j] = qv;
        }
    }
    __syncthreads();
    if (tid < HH) {
        float a = sRs[0][tid] + sRs[1][tid] + sRs[2][tid] + sRs[3][tid];
        float b = sRq[0][tid] + sRq[1][tid] + sRq[2][tid] + sRq[3][tid];
        atomicAdd(&g_sum[tid], a);
        atomicAdd(&g_sumsq[tid], b);
    }
}

__global__ void k_bnparam(const float* __restrict__ gamma, const float* __restrict__ beta) {
    int j = threadIdx.x;
    if (j < HH) {
        float inv_n = 1.f / (float)NN;
        float mean = g_sum[j] * inv_n;
        float var  = g_sumsq[j] * inv_n - mean * mean;
        float rstd = rsqrtf(var + EPSBN);
        float sc = gamma[j] * rstd;
        g_scale[j] = sc;
        g_shift[j] = beta[j] - mean * sc;
    }
}

// y = relu(h*scale + shift) @ Wmix[64,6] + bmix
__global__ __launch_bounds__(256) void k_final(const float* __restrict__ Wmix,
                                               const float* __restrict__ bmix,
                                               float* __restrict__ out) {
    __shared__ float sWm[HH * OD];
    __shared__ float sSc[HH], sSh[HH], sB[OD];
    int tid = threadIdx.x;
    for (int i = tid; i < HH * OD; i += 256) sWm[i] = Wmix[i];
    if (tid < HH) { sSc[tid] = g_scale[tid]; sSh[tid] = g_shift[tid]; }
    if (tid < OD) sB[tid] = bmix[tid];
    __syncthreads();

    int n = blockIdx.x * 256 + tid;
    if (n >= NN) return;

    float o0 = sB[0], o1 = sB[1], o2 = sB[2], o3 = sB[3], o4 = sB[4], o5 = sB[5];
    const float4* hp = (const float4*)(g_h + (size_t)n * HH);
#pragma unroll
    for (int j4 = 0; j4 < 16; j4++) {
        float4 hv = hp[j4];
        float hv4[4] = {hv.x, hv.y, hv.z, hv.w};
#pragma unroll
        for (int t = 0; t < 4; t++) {
            int j = 4 * j4 + t;
            float val = fmaxf(hv4[t] * sSc[j] + sSh[j], 0.f);
            const float* wm = &sWm[j * OD];
            o0 += val * wm[0]; o1 += val * wm[1]; o2 += val * wm[2];
            o3 += val * wm[3]; o4 += val * wm[4]; o5 += val * wm[5];
        }
    }
    float* op = out + (size_t)n * OD;
    op[0] = o0; op[1] = o1; op[2] = o2; op[3] = o3; op[4] = o4; op[5] = o5;
}

// ---------------- launch ----------------
extern "C" void kernel_launch(void* const* d_in, const int* in_sizes, int n_in,
                              void* d_out, int out_size) {
    const float* x     = (const float*)d_in[0];
    const int*   ei    = (const int*)  d_in[1];
    const float* W1    = (const float*)d_in[2];
    const float* b1    = (const float*)d_in[3];
    const float* gamma = (const float*)d_in[4];
    const float* beta  = (const float*)d_in[5];
    const float* Wmix  = (const float*)d_in[6];
    const float* bmix  = (const float*)d_in[7];
    float* out = (float*)d_out;

    const int* row = ei;        // edge_index[0]
    const int* col = ei + EE;   // edge_index[1]

    const int TB = 256;
    int gN  = (NN + TB - 1) / TB;
    int gE4 = (EE / 4 + TB - 1) / TB;
    int gI  = (NN * FIN / 4 + TB - 1) / TB;
    int gP  = (2 * EE + TB - 1) / TB;

    k_zero<<<gN, TB>>>();
    k_deg<<<gE4, TB>>>((const int4*)col);
    k_dis<<<gN, TB>>>();
    k_norm<<<gE4, TB>>>((const int4*)row, (const int4*)col);

    // T1 = prop(x)
    k_init<<<gI, TB>>>(0, -1, x, 0.f);
    k_prop<<<gP, TB>>>(0, -1, x, row, col, 1.f);
    // T2 = 2*prop(T1) - x
    k_init<<<gI, TB>>>(1, -1, x, -1.f);
    k_prop<<<gP, TB>>>(1, 0, x, row, col, 2.f);
    // T3 = 2*prop(T2) - T1
    k_init<<<gI, TB>>>(2, 0, x, -1.f);
    k_prop<<<gP, TB>>>(2, 1, x, row, col, 2.f);
    // T4 = 2*prop(T3) - T2
    k_init<<<gI, TB>>>(3, 1, x, -1.f);
    k_prop<<<gP, TB>>>(3, 2, x, row, col, 2.f);
    // T5 = 2*prop(T4) - T3
    k_init<<<gI, TB>>>(4, 2, x, -1.f);
    k_prop<<<gP, TB>>>(4, 3, x, row, col, 2.f);

    // stacked GEMM + BN stats
    k_gemm<<<(NN + 127) / 128, 128>>>(x, W1, b1);
    k_bnparam<<<1, HH>>>(gamma, beta);
    k_final<<<(NN + TB - 1) / TB, TB>>>(Wmix, bmix, out);
}